// round 11
// baseline (speedup 1.0000x reference)
#include <cuda_runtime.h>

// DiscreteContinuousConvS2: fused DISCO gather + channel-contraction GEMM.
// R8: psi via single warp-load + shfl broadcast (off-crossbar), GEMM remapped
// to 4f x 8wo per thread (halves y-broadcast wavefronts), weight staged from
// pre-transposed [ck][f] buffer.

namespace {
constexpr int B_  = 2;
constexpr int C_  = 64;   // C_in
constexpr int F_  = 64;   // C_out
constexpr int H_  = 181;  // nlat
constexpr int W_  = 360;  // nlon
constexpr int K_  = 9;    // kernel functions
constexpr int J_  = 24;   // nnz per (k, lat_out)

constexpr int CCH = 8;            // channels per chunk
constexpr int NCH = C_ / CCH;     // 8 chunks
constexpr int WT  = 128;          // wo tile width
constexpr int SXP = W_ + WT;      // 488: wrap-padded x row pitch (floats)
constexpr int SXC = 3 * SXP;      // 1464: per-channel slab (3 lat rows)
constexpr int CKL = CCH * K_;     // 72 (c,k) pairs per chunk
constexpr int NT  = 256;          // threads per CTA

constexpr int SX_FLOATS = CCH * SXC;      // 11712
constexpr int SY_FLOATS = CKL * WT;       // 9216
constexpr int SW_FLOATS = CKL * F_;       // 4608  ([ck][f])
constexpr size_t SMEM_BYTES =
    (size_t)(SX_FLOATS + SY_FLOATS + SW_FLOATS) * 4 + (size_t)K_ * J_ * 8;

constexpr int ROW4 = 122;                 // float4s per staged row (90 + 32 wrap)
constexpr int NROW = CCH * 3;             // 24 staged rows per chunk
}

using ull = unsigned long long;

__device__ __forceinline__ void ffma2(ull& d, ull a, ull b) {
  asm("fma.rn.f32x2 %0, %1, %2, %0;" : "+l"(d) : "l"(a), "l"(b));
}
__device__ __forceinline__ ull splat2(float w) {
  ull r;
  asm("mov.b64 %0, {%1, %1};" : "=l"(r) : "f"(w));
  return r;
}

// weight transposed to [c*K+k][f] so per-chunk smem fill is contiguous
__device__ float g_wT[C_ * K_ * F_];

__global__ void transpose_w_kernel(const float* __restrict__ w) {
  int i = blockIdx.x * blockDim.x + threadIdx.x;
  if (i < C_ * K_ * F_) {
    int f  = i & (F_ - 1);
    int ck = i >> 6;
    // w layout: [F][C][K] flat f*576 + ck  ->  g_wT[ck*64 + f]
    g_wT[i] = w[f * (C_ * K_) + ck];
  }
}

__global__ __launch_bounds__(NT, 2)
void disco_kernel(const float* __restrict__ x,
                  const float* __restrict__ psi_vals,
                  const float* __restrict__ bias,
                  const int*   __restrict__ psi_lat_in,
                  const int*   __restrict__ psi_lon_in,
                  float*       __restrict__ out) {
  extern __shared__ float smem[];
  float*  sx = smem;                       // [CCH][3][SXP]
  float*  sy = sx + SX_FLOATS;             // [CKL][WT]
  float*  sw = sy + SY_FLOATS;             // [CKL][F_]  (w[ck][f])
  float2* se = (float2*)(sw + SW_FLOATS);  // [K_*J_] {psi, offset-as-int}

  const int t    = threadIdx.x;
  const int lane = t & 31;
  const int warp = t >> 5;
  const int ho   = blockIdx.y;
  const int b    = blockIdx.z;
  // 3 tiles: 0, 128, and last shifted to 232 (24-col overlap recompute)
  const int wb = (blockIdx.x == 2) ? (W_ - WT) : blockIdx.x * WT;

  // ---- build per-ho entry table, rebased by wb ----
  if (t < K_ * J_) {
    int k = t / J_;
    int j = t - k * J_;
    int e = (k * H_ + ho) * J_ + j;
    int li  = psi_lat_in[e] - (ho - 1);       // local lat row 0..2
    int lon = psi_lon_in[e] + wb;
    if (lon >= W_) lon -= W_;                 // rebased start lon (0..359)
    int off = li * SXP + lon;                 // smem offset within channel slab
    se[t] = make_float2(psi_vals[e], __int_as_float(off));
  }

  // ---- GEMM mapping: thread owns f ∈ {4g..4g+3}, wo = sp*8 .. sp*8+7 ----
  const int g   = lane & 15;                 // f quad index
  const int sp  = (warp << 1) | (lane >> 4); // wo span 0..15
  const int wo0 = sp << 3;
  ull acc[4][4];                             // [fi][wo-pair]
#pragma unroll
  for (int fi = 0; fi < 4; fi++) {
    ull bv = splat2(bias[(g << 2) + fi]);
#pragma unroll
    for (int p = 0; p < 4; p++) acc[fi][p] = bv;
  }

  for (int ch = 0; ch < NCH; ch++) {
    const int c0 = ch * CCH;
    __syncthreads();  // prev GEMM done reading sy/sw; entry table ready

    // ---- stage x slice (float4): 24 rows of 122 float4 (360 + 128 wrap) ----
    for (int i = t; i < NROW * ROW4; i += NT) {
      int row = i / ROW4;              // c*3 + l
      int q   = i - row * ROW4;        // 0..121
      int c   = row / 3;
      int l   = row - c * 3;
      int hr  = ho - 1 + l;
      hr = (hr < 0) ? 0 : (hr > H_ - 1 ? H_ - 1 : hr);
      const float4* src =
          (const float4*)(x + ((size_t)(b * C_ + c0 + c) * H_ + hr) * W_);
      int gq = (q < 90) ? q : (q - 90);          // wrap tail reads cols 0..127
      ((float4*)(sx + c * SXC + l * SXP))[q] = src[gq];
    }
    // ---- stage weight chunk [72][64], contiguous from g_wT ----
    {
      const float4* wsrc = (const float4*)(g_wT + c0 * K_ * F_);
      float4* wdst = (float4*)sw;
      for (int i = t; i < SW_FLOATS / 4; i += NT) wdst[i] = wsrc[i];
    }
    __syncthreads();

    // ---- gather: warp = one channel; psi via shfl broadcast ----
    {
      const float* base = sx + warp * SXC;
#pragma unroll
      for (int k = 0; k < K_; k++) {
        // lane j<24 holds entry (k, j); broadcast via shfl (no crossbar)
        float2 my = make_float2(0.f, 0.f);
        if (lane < J_) my = se[k * J_ + lane];
        float a0 = 0.f, a1 = 0.f, a2 = 0.f, a3 = 0.f;
#pragma unroll
        for (int j = 0; j < J_; j++) {
          float ps  = __shfl_sync(0xffffffffu, my.x, j);
          int   off = __shfl_sync(0xffffffffu, __float_as_int(my.y), j);
          const float* p = base + off + lane;
          a0 = fmaf(ps, p[0],  a0);
          a1 = fmaf(ps, p[32], a1);
          a2 = fmaf(ps, p[64], a2);
          a3 = fmaf(ps, p[96], a3);
        }
        float* yo = sy + (warp * K_ + k) * WT + lane;
        yo[0]  = a0;
        yo[32] = a1;
        yo[64] = a2;
        yo[96] = a3;
      }
    }
    __syncthreads();

    // ---- GEMM (FFMA2): acc[f][wo-pair] += w[ck][f] * y[ck][wo-pair] ----
#pragma unroll 2
    for (int ck = 0; ck < CKL; ck++) {
      float4 w4 = *(const float4*)(sw + ck * F_ + (g << 2));
      const ulonglong2* yp = (const ulonglong2*)(sy + ck * WT + wo0);
      ulonglong2 p0 = yp[0], p1 = yp[1];
      ull w0 = splat2(w4.x), w1 = splat2(w4.y);
      ull w2 = splat2(w4.z), w3 = splat2(w4.w);
      ffma2(acc[0][0], w0, p0.x); ffma2(acc[0][1], w0, p0.y);
      ffma2(acc[0][2], w0, p1.x); ffma2(acc[0][3], w0, p1.y);
      ffma2(acc[1][0], w1, p0.x); ffma2(acc[1][1], w1, p0.y);
      ffma2(acc[1][2], w1, p1.x); ffma2(acc[1][3], w1, p1.y);
      ffma2(acc[2][0], w2, p0.x); ffma2(acc[2][1], w2, p0.y);
      ffma2(acc[2][2], w2, p1.x); ffma2(acc[2][3], w2, p1.y);
      ffma2(acc[3][0], w3, p0.x); ffma2(acc[3][1], w3, p0.y);
      ffma2(acc[3][2], w3, p1.x); ffma2(acc[3][3], w3, p1.y);
    }
  }

  // ---- write out[b][f][ho][wb + wo0 .. +7] for f = 4g..4g+3 ----
  {
    int wcol = wb + wo0;
#pragma unroll
    for (int fi = 0; fi < 4; fi++) {
      int f = (g << 2) + fi;
      ull* o = (ull*)(out + (((size_t)(b * F_ + f) * H_ + ho) * W_ + wcol));
      o[0] = acc[fi][0];
      o[1] = acc[fi][1];
      o[2] = acc[fi][2];
      o[3] = acc[fi][3];
    }
  }
}

extern "C" void kernel_launch(void* const* d_in, const int* in_sizes, int n_in,
                              void* d_out, int out_size) {
  const float* x          = (const float*)d_in[0];
  const float* psi_vals   = (const float*)d_in[1];
  const float* weight     = (const float*)d_in[2];
  const float* bias       = (const float*)d_in[3];
  const int*   psi_lat_in = (const int*)  d_in[6];
  const int*   psi_lon_in = (const int*)  d_in[7];
  float*       out        = (float*)d_out;

  transpose_w_kernel<<<(C_ * K_ * F_ + NT - 1) / NT, NT>>>(weight);

  cudaFuncSetAttribute(disco_kernel,
                       cudaFuncAttributeMaxDynamicSharedMemorySize,
                       (int)SMEM_BYTES);
  dim3 grid(3, H_, B_);
  disco_kernel<<<grid, NT, SMEM_BYTES>>>(x, psi_vals, bias,
                                         psi_lat_in, psi_lon_in, out);
}